// round 15
// baseline (speedup 1.0000x reference)
#include <cuda_runtime.h>
#include <math.h>

#define NN 100000
#define EE 400000
#define HH 128

typedef unsigned long long u64;

// ---- scratch (device globals: allocation-free) ----
__device__ float g_upd[NN * HH];        // scatter accumulator [N,128]
__device__ float g_Us[NN * 256];        // per-node src tables: [U1s | Ugs]
__device__ float g_Ud[NN * 256];        // per-node dst tables: [U1d | Ugd]
__device__ float g_As[128 * 128];       // W_src@W1a
__device__ float g_Gs[128 * 128];       // W_src@Wg1a
__device__ float g_Ad[128 * 128];       // W_dst@W1b
__device__ float g_Gd[128 * 128];       // W_dst@Wg1b
__device__ float g_fb[4][128];          // folded biases

__device__ __forceinline__ float4 ld4(const float* p) { return *reinterpret_cast<const float4*>(p); }
__device__ __forceinline__ void   st4(float* p, float4 v) { *reinterpret_cast<float4*>(p) = v; }
__device__ __forceinline__ ulonglong2 ld2u64(const float* p) {
    return *reinterpret_cast<const ulonglong2*>(p);
}

__device__ __forceinline__ u64 bcast2(float a) {
    u64 r; asm("mov.b64 %0, {%1, %1};" : "=l"(r) : "f"(a)); return r;
}
__device__ __forceinline__ void ffma2(u64& d, u64 a, u64 b) {
    asm("fma.rn.f32x2 %0, %1, %2, %0;" : "+l"(d) : "l"(a), "l"(b));
}
__device__ __forceinline__ float2 unpk(u64 v) {
    float2 f; asm("mov.b64 {%0, %1}, %2;" : "=f"(f.x), "=f"(f.y) : "l"(v)); return f;
}

__device__ __forceinline__ float gelu_exact(float x) {
    return 0.5f * x * (1.0f + erff(x * 0.70710678118654752440f));
}

#define PFMA8(ACC, AP, BA, BB)       \
    ffma2(ACC[0], AP, BA.x);         \
    ffma2(ACC[1], AP, BA.y);         \
    ffma2(ACC[2], AP, BB.x);         \
    ffma2(ACC[3], AP, BB.y);

#define ZERO_ACC2(A)                                  \
    _Pragma("unroll") for (int _r = 0; _r < 4; _r++)  \
    _Pragma("unroll") for (int _j = 0; _j < 4; _j++) A[_r][_j] = 0ULL;

#define UNPACK8(X, ACCR)                       \
    { float2 _p;                               \
      _p = unpk(ACCR[0]); X[0] = _p.x; X[1] = _p.y; \
      _p = unpk(ACCR[1]); X[2] = _p.x; X[3] = _p.y; \
      _p = unpk(ACCR[2]); X[4] = _p.x; X[5] = _p.y; \
      _p = unpk(ACCR[3]); X[6] = _p.x; X[7] = _p.y; }

// ---------------------------------------------------------------------------
// 64x128 GEMM tile (packed f32x2): C[64,128] = A0@W0   (R9-proven structure)
// ---------------------------------------------------------------------------
__device__ __forceinline__ void gemm64p(
    const float* __restrict__ A0,
    const float* __restrict__ W0g,
    float* __restrict__ sW,          // smem, >=1024 floats used
    u64 acc[4][4], int tid)
{
    const int ty = tid >> 4, tx = tid & 15;
    const int wr = tid >> 5;
    const int wc = (tid & 31) << 2;

#pragma unroll 1
    for (int kc = 0; kc < 16; kc++) {
        __syncthreads();
        st4(sW + wr * 128 + wc, ld4(W0g + (kc * 8 + wr) * 128 + wc));
        __syncthreads();
#pragma unroll
        for (int k4 = 0; k4 < 8; k4 += 4) {
            float4 a0[4];
#pragma unroll
            for (int r = 0; r < 4; r++)
                a0[r] = ld4(A0 + (ty * 4 + r) * 128 + kc * 8 + k4);
#pragma unroll
            for (int kk = 0; kk < 4; kk++) {
                const int k = k4 + kk;
                ulonglong2 b0a = ld2u64(sW + k * 128 + tx * 4);
                ulonglong2 b0b = ld2u64(sW + k * 128 + 64 + tx * 4);
#pragma unroll
                for (int r = 0; r < 4; r++) {
                    u64 ap = bcast2((&a0[r].x)[kk]);
                    PFMA8(acc[r], ap, b0a, b0b);
                }
            }
        }
    }
}

// Dual-OUTPUT variant: accS = A@W0, accD = A@W1 (shares A loads).
__device__ __forceinline__ void gemm64p_2w(
    const float* __restrict__ A0,
    const float* __restrict__ W0g, const float* __restrict__ W1g,
    float* __restrict__ sW, u64 accS[4][4], u64 accD[4][4], int tid)
{
    const int ty = tid >> 4, tx = tid & 15;
    const int wr = tid >> 5;
    const int wc = (tid & 31) << 2;

#pragma unroll 1
    for (int kc = 0; kc < 16; kc++) {
        __syncthreads();
        st4(sW + wr * 128 + wc, ld4(W0g + (kc * 8 + wr) * 128 + wc));
        st4(sW + 1024 + wr * 128 + wc, ld4(W1g + (kc * 8 + wr) * 128 + wc));
        __syncthreads();
#pragma unroll
        for (int k4 = 0; k4 < 8; k4 += 4) {
            float4 a0[4];
#pragma unroll
            for (int r = 0; r < 4; r++)
                a0[r] = ld4(A0 + (ty * 4 + r) * 128 + kc * 8 + k4);
#pragma unroll
            for (int kk = 0; kk < 4; kk++) {
                const int k = k4 + kk;
                ulonglong2 b0a = ld2u64(sW + k * 128 + tx * 4);
                ulonglong2 b0b = ld2u64(sW + k * 128 + 64 + tx * 4);
                ulonglong2 b1a = ld2u64(sW + 1024 + k * 128 + tx * 4);
                ulonglong2 b1b = ld2u64(sW + 1024 + k * 128 + 64 + tx * 4);
#pragma unroll
                for (int r = 0; r < 4; r++) {
                    u64 ap = bcast2((&a0[r].x)[kk]);
                    PFMA8(accS[r], ap, b0a, b0b);
                    PFMA8(accD[r], ap, b1a, b1b);
                }
            }
        }
    }
}

// ---------------------------------------------------------------------------
__global__ void zero_upd_kernel() {
    int i = blockIdx.x * blockDim.x + threadIdx.x;
    if (i < NN * HH / 4) reinterpret_cast<float4*>(g_upd)[i] = make_float4(0.f, 0.f, 0.f, 0.f);
}

// Composite weights: g_As = Ws@W1a, g_Gs = Ws@Wg1a, g_Ad = Wd@W1b, g_Gd = Wd@Wg1b
__global__ __launch_bounds__(256, 2) void compose_kernel(
    const float* __restrict__ Ws, const float* __restrict__ Wd,
    const float* __restrict__ W1a, const float* __restrict__ Wg1a,
    const float* __restrict__ W1b, const float* __restrict__ Wg1b)
{
    __shared__ float sA[64 * 128];
    __shared__ float sW[1024];
    const int mat = blockIdx.x >> 1, half = blockIdx.x & 1;
    const float* L = (mat < 2) ? Ws : Wd;
    const float* R = (mat == 0) ? W1a : (mat == 1) ? Wg1a : (mat == 2) ? W1b : Wg1b;
    float* O = (mat == 0) ? g_As : (mat == 1) ? g_Gs : (mat == 2) ? g_Ad : g_Gd;

    const int tid = threadIdx.x, warp = tid >> 5, lane = tid & 31;
    const int ty = tid >> 4, tx = tid & 15;
#pragma unroll
    for (int i = 0; i < 8; i++) {
        int r = warp + i * 8;
        st4(sA + r * 128 + lane * 4, ld4(L + (half * 64 + r) * 128 + lane * 4));
    }
    u64 acc[4][4];
    ZERO_ACC2(acc);
    gemm64p(sA, R, sW, acc, tid);
#pragma unroll
    for (int r = 0; r < 4; r++) {
        int row = half * 64 + ty * 4 + r;
        float x[8]; UNPACK8(x, acc[r]);
        st4(O + row * 128 + tx * 4,      make_float4(x[0], x[1], x[2], x[3]));
        st4(O + row * 128 + 64 + tx * 4, make_float4(x[4], x[5], x[6], x[7]));
    }
}

// folded biases: g_fb[0]=b_src@W1a, [1]=b_src@Wg1a, [2]=b_dst@W1b, [3]=b_dst@Wg1b
__global__ void bias_kernel(
    const float* __restrict__ bsrc, const float* __restrict__ bdst,
    const float* __restrict__ W1a, const float* __restrict__ Wg1a,
    const float* __restrict__ W1b, const float* __restrict__ Wg1b)
{
    const int mat = blockIdx.x, n = threadIdx.x;
    const float* bv = (mat < 2) ? bsrc : bdst;
    const float* R = (mat == 0) ? W1a : (mat == 1) ? Wg1a : (mat == 2) ? W1b : Wg1b;
    float s = 0.f;
    for (int j = 0; j < 128; j++) s = fmaf(bv[j], R[j * 128 + n], s);
    g_fb[mat][n] = s;
}

// Node tables: g_Us[n] = [feat@As + fb0 | feat@Gs + fb1]; g_Ud similarly.
__global__ __launch_bounds__(256, 2) void node_kernel(const float* __restrict__ feat)
{
    __shared__ float sF[64 * 128];
    __shared__ float sW[2 * 1024];
    const int tid = threadIdx.x, warp = tid >> 5, lane = tid & 31;
    const int ty = tid >> 4, tx = tid & 15;
    const int which = (blockIdx.x >= 1563) ? 1 : 0;
    const size_t row0 = (size_t)(blockIdx.x - which * 1563) * 64;

    const float* WA = which ? g_Ad : g_As;
    const float* WG = which ? g_Gd : g_Gs;
    const float* f1 = which ? g_fb[2] : g_fb[0];
    const float* fg = which ? g_fb[3] : g_fb[1];
    float* table = which ? g_Ud : g_Us;

#pragma unroll
    for (int i = 0; i < 8; i++) {
        int r = warp + i * 8;
        size_t gr = row0 + r;
        float4 v = make_float4(0.f, 0.f, 0.f, 0.f);
        if (gr < NN) v = ld4(feat + gr * 128 + lane * 4);
        st4(sF + r * 128 + lane * 4, v);
    }
    u64 accU[4][4], accG[4][4];
    ZERO_ACC2(accU); ZERO_ACC2(accG);
    gemm64p_2w(sF, WA, WG, sW, accU, accG, tid);

    float4 b10 = ld4(f1 + tx * 4), b11 = ld4(f1 + 64 + tx * 4);
    float4 bg0 = ld4(fg + tx * 4), bg1v = ld4(fg + 64 + tx * 4);
#pragma unroll
    for (int r = 0; r < 4; r++) {
        size_t gr = row0 + ty * 4 + r;
        if (gr < NN) {
            float xu[8], xg[8];
            UNPACK8(xu, accU[r]); UNPACK8(xg, accG[r]);
            st4(table + gr * 256 + tx * 4,
                make_float4(xu[0] + b10.x, xu[1] + b10.y, xu[2] + b10.z, xu[3] + b10.w));
            st4(table + gr * 256 + 64 + tx * 4,
                make_float4(xu[4] + b11.x, xu[5] + b11.y, xu[6] + b11.z, xu[7] + b11.w));
            st4(table + gr * 256 + 128 + tx * 4,
                make_float4(xg[0] + bg0.x, xg[1] + bg0.y, xg[2] + bg0.z, xg[3] + bg0.w));
            st4(table + gr * 256 + 192 + tx * 4,
                make_float4(xg[4] + bg1v.x, xg[5] + bg1v.y, xg[6] + bg1v.z, xg[7] + bg1v.w));
        }
    }
}

// Fused edge pipeline: gather precomputed linear parts, 2 GEMMs, LN, gated scatter.
__global__ __launch_bounds__(256, 3) void edge_kernel(
    const int* __restrict__ esrc, const int* __restrict__ edst,
    const float* __restrict__ b1,
    const float* __restrict__ W2,  const float* __restrict__ b2,
    const float* __restrict__ W3,  const float* __restrict__ b3,
    const float* __restrict__ lng, const float* __restrict__ lnb,
    const float* __restrict__ bg1, const float* __restrict__ Wg2,
    const float* __restrict__ bg2)
{
    __shared__ float sH[64 * 128];
    __shared__ float sW[1024];
    __shared__ float sGate[64];
    __shared__ int   sDst[64];

    const int tid = threadIdx.x, warp = tid >> 5, lane = tid & 31;
    const int ty = tid >> 4, tx = tid & 15;
    const int e0 = blockIdx.x * 64;

    // ---- gather + h1 + gate pre-reduction ----
    {
        float4 b1v = ld4(b1 + lane * 4);
        float4 bgv = ld4(bg1 + lane * 4);
        float4 wgv = ld4(Wg2 + lane * 4);
#pragma unroll 1
        for (int i = 0; i < 8; i++) {
            int r = warp * 8 + i;
            int s = esrc[e0 + r];
            int d = edst[e0 + r];
            const float* us = g_Us + (size_t)s * 256;
            const float* ud = g_Ud + (size_t)d * 256;
            float4 a = ld4(us + lane * 4);
            float4 bq = ld4(ud + lane * 4);
            float4 a2 = ld4(us + 128 + lane * 4);
            float4 b2q = ld4(ud + 128 + lane * 4);
            float4 h;
            h.x = gelu_exact(a.x + bq.x + b1v.x);
            h.y = gelu_exact(a.y + bq.y + b1v.y);
            h.z = gelu_exact(a.z + bq.z + b1v.z);
            h.w = gelu_exact(a.w + bq.w + b1v.w);
            st4(sH + r * 128 + lane * 4, h);
            float sg = gelu_exact(a2.x + b2q.x + bgv.x) * wgv.x
                     + gelu_exact(a2.y + b2q.y + bgv.y) * wgv.y
                     + gelu_exact(a2.z + b2q.z + bgv.z) * wgv.z
                     + gelu_exact(a2.w + b2q.w + bgv.w) * wgv.w;
#pragma unroll
            for (int off = 1; off < 32; off <<= 1)
                sg += __shfl_xor_sync(0xffffffffu, sg, off);
            if (lane == 0) { sGate[r] = sg; sDst[r] = d; }
        }
    }
    // (gemm64p's leading __syncthreads orders gather writes before reads)

    u64 acc[4][4];

    // ---- h2 = gelu(h1@W2 + b2) -> sH (overwrite after barrier) ----
    ZERO_ACC2(acc);
    gemm64p(sH, W2, sW, acc, tid);
    __syncthreads();   // all reads of h1 done before overwrite
    {
        float4 bb0 = ld4(b2 + tx * 4), bb1 = ld4(b2 + 64 + tx * 4);
#pragma unroll
        for (int r = 0; r < 4; r++) {
            int row = ty * 4 + r;
            float x[8]; UNPACK8(x, acc[r]);
            float4 h;
            h.x = gelu_exact(x[0] + bb0.x); h.y = gelu_exact(x[1] + bb0.y);
            h.z = gelu_exact(x[2] + bb0.z); h.w = gelu_exact(x[3] + bb0.w);
            st4(sH + row * 128 + tx * 4, h);
            h.x = gelu_exact(x[4] + bb1.x); h.y = gelu_exact(x[5] + bb1.y);
            h.z = gelu_exact(x[6] + bb1.z); h.w = gelu_exact(x[7] + bb1.w);
            st4(sH + row * 128 + 64 + tx * 4, h);
        }
    }

    // ---- m = layernorm(h2@W3 + b3); msg = gate*m; vector-red scatter ----
    ZERO_ACC2(acc);
    gemm64p(sH, W3, sW, acc, tid);
    {
        float bg2v = bg2[0];
        float4 b30 = ld4(b3 + tx * 4),  b31 = ld4(b3 + 64 + tx * 4);
        float4 g0  = ld4(lng + tx * 4), g1  = ld4(lng + 64 + tx * 4);
        float4 e0v = ld4(lnb + tx * 4), e1v = ld4(lnb + 64 + tx * 4);
#pragma unroll
        for (int r = 0; r < 4; r++) {
            int row = ty * 4 + r;
            float x[8]; UNPACK8(x, acc[r]);
            x[0] += b30.x; x[1] += b30.y; x[2] += b30.z; x[3] += b30.w;
            x[4] += b31.x; x[5] += b31.y; x[6] += b31.z; x[7] += b31.w;
            float s = 0.f, ss = 0.f;
#pragma unroll
            for (int j = 0; j < 8; j++) { s += x[j]; ss += x[j] * x[j]; }
#pragma unroll
            for (int off = 1; off < 16; off <<= 1) {
                s  += __shfl_xor_sync(0xffffffffu, s, off);
                ss += __shfl_xor_sync(0xffffffffu, ss, off);
            }
            float m = s * 0.0078125f;
            float var = ss * 0.0078125f - m * m;
            float rstd = rsqrtf(var + 1e-5f);
            float gv = 1.0f / (1.0f + expf(-(sGate[row] + bg2v)));
            float* up = g_upd + (size_t)sDst[row] * 128;
            float4 v0 = make_float4(((x[0] - m) * rstd * g0.x + e0v.x) * gv,
                                    ((x[1] - m) * rstd * g0.y + e0v.y) * gv,
                                    ((x[2] - m) * rstd * g0.z + e0v.z) * gv,
                                    ((x[3] - m) * rstd * g0.w + e0v.w) * gv);
            float4 v1 = make_float4(((x[4] - m) * rstd * g1.x + e1v.x) * gv,
                                    ((x[5] - m) * rstd * g1.y + e1v.y) * gv,
                                    ((x[6] - m) * rstd * g1.z + e1v.z) * gv,
                                    ((x[7] - m) * rstd * g1.w + e1v.w) * gv);
            atomicAdd(reinterpret_cast<float4*>(up + tx * 4), v0);
            atomicAdd(reinterpret_cast<float4*>(up + 64 + tx * 4), v1);
        }
    }
}

// out = upd@W_out + b_out
__global__ __launch_bounds__(256, 2) void out_kernel(
    const float* __restrict__ Wout, const float* __restrict__ bout,
    float* __restrict__ out)
{
    __shared__ float sU[64 * 128];
    __shared__ float sW[1024];
    const int tid = threadIdx.x, warp = tid >> 5, lane = tid & 31;
    const int ty = tid >> 4, tx = tid & 15;
    const size_t row0 = (size_t)blockIdx.x * 64;

#pragma unroll
    for (int i = 0; i < 8; i++) {
        int r = warp + i * 8;
        size_t gr = row0 + r;
        float4 v = make_float4(0.f, 0.f, 0.f, 0.f);
        if (gr < NN) v = ld4(g_upd + gr * 128 + lane * 4);
        st4(sU + r * 128 + lane * 4, v);
    }
    u64 acc[4][4];
    ZERO_ACC2(acc);
    gemm64p(sU, Wout, sW, acc, tid);

    float4 b0 = ld4(bout + tx * 4), b1v = ld4(bout + 64 + tx * 4);
#pragma unroll
    for (int r = 0; r < 4; r++) {
        size_t gr = row0 + ty * 4 + r;
        if (gr < NN) {
            float x[8]; UNPACK8(x, acc[r]);
            st4(out + gr * 128 + tx * 4,
                make_float4(x[0] + b0.x, x[1] + b0.y, x[2] + b0.z, x[3] + b0.w));
            st4(out + gr * 128 + 64 + tx * 4,
                make_float4(x[4] + b1v.x, x[5] + b1v.y, x[6] + b1v.z, x[7] + b1v.w));
        }
    }
}

extern "C" void kernel_launch(void* const* d_in, const int* in_sizes, int n_in,
                              void* d_out, int out_size)
{
    const float* feat  = (const float*)d_in[0];
    const int*   esrc  = (const int*)d_in[1];
    const int*   edst  = (const int*)d_in[2];
    const float* W_src = (const float*)d_in[3];
    const float* b_src = (const float*)d_in[4];
    const float* W_dst = (const float*)d_in[5];
    const float* b_dst = (const float*)d_in[6];
    const float* W1a   = (const float*)d_in[7];
    const float* W1b   = (const float*)d_in[8];
    const float* b1    = (const float*)d_in[9];
    const float* W2    = (const float*)d_in[10];
    const float* b2    = (const float*)d_in[11];
    const float* W3    = (const float*)d_in[12];
    const float* b3    = (const float*)d_in[13];
    const float* ln_g  = (const float*)d_in[14];
    const float* ln_b  = (const float*)d_in[15];
    const float* Wg1a  = (const float*)d_in[16];
    const float* Wg1b  = (const float*)d_in[17];
    const float* bg1   = (const float*)d_in[18];
    const float* Wg2   = (const float*)d_in[19];
    const float* bg2   = (const float*)d_in[20];
    const float* W_out = (const float*)d_in[21];
    const float* b_out = (const float*)d_in[22];
    float* out = (float*)d_out;

    compose_kernel<<<8, 256>>>(W_src, W_dst, W1a, Wg1a, W1b, Wg1b);
    bias_kernel<<<4, 128>>>(b_src, b_dst, W1a, Wg1a, W1b, Wg1b);
    zero_upd_kernel<<<(NN * HH / 4 + 255) / 256, 256>>>();
    node_kernel<<<2 * 1563, 256>>>(feat);
    edge_kernel<<<EE / 64, 256>>>(esrc, edst, b1, W2, b2, W3, b3,
                                  ln_g, ln_b, bg1, Wg2, bg2);
    out_kernel<<<(NN + 63) / 64, 256>>>(W_out, b_out, out);
}

// round 17
// speedup vs baseline: 1.6024x; 1.6024x over previous
#include <cuda_runtime.h>
#include <math.h>

#define NN 100000
#define EE 400000
#define HH 128

typedef unsigned long long u64;

// ---- scratch (device globals: allocation-free) ----
__device__ float g_upd[NN * HH];        // scatter accumulator [N,128]
__device__ float g_Us[NN * 256];        // per-node src tables: [U1s | Ugs]
__device__ float g_Ud[NN * 256];        // per-node dst tables: [U1d | Ugd]
__device__ float g_As[128 * 128];       // W_src@W1a
__device__ float g_Gs[128 * 128];       // W_src@Wg1a
__device__ float g_Ad[128 * 128];       // W_dst@W1b
__device__ float g_Gd[128 * 128];       // W_dst@Wg1b
__device__ float g_fb[4][128];          // folded biases

__device__ __forceinline__ float4 ld4(const float* p) { return *reinterpret_cast<const float4*>(p); }
__device__ __forceinline__ void   st4(float* p, float4 v) { *reinterpret_cast<float4*>(p) = v; }
__device__ __forceinline__ ulonglong2 ld2u64(const float* p) {
    return *reinterpret_cast<const ulonglong2*>(p);
}

__device__ __forceinline__ u64 bcast2(float a) {
    u64 r; asm("mov.b64 %0, {%1, %1};" : "=l"(r) : "f"(a)); return r;
}
__device__ __forceinline__ void ffma2(u64& d, u64 a, u64 b) {
    asm("fma.rn.f32x2 %0, %1, %2, %0;" : "+l"(d) : "l"(a), "l"(b));
}
__device__ __forceinline__ float2 unpk(u64 v) {
    float2 f; asm("mov.b64 {%0, %1}, %2;" : "=f"(f.x), "=f"(f.y) : "l"(v)); return f;
}

__device__ __forceinline__ float gelu_exact(float x) {
    return 0.5f * x * (1.0f + erff(x * 0.70710678118654752440f));
}

#define PFMA8(ACC, AP, BA, BB)       \
    ffma2(ACC[0], AP, BA.x);         \
    ffma2(ACC[1], AP, BA.y);         \
    ffma2(ACC[2], AP, BB.x);         \
    ffma2(ACC[3], AP, BB.y);

#define ZERO_ACC2(A)                                  \
    _Pragma("unroll") for (int _r = 0; _r < 4; _r++)  \
    _Pragma("unroll") for (int _j = 0; _j < 4; _j++) A[_r][_j] = 0ULL;

#define UNPACK8(X, ACCR)                       \
    { float2 _p;                               \
      _p = unpk(ACCR[0]); X[0] = _p.x; X[1] = _p.y; \
      _p = unpk(ACCR[1]); X[2] = _p.x; X[3] = _p.y; \
      _p = unpk(ACCR[2]); X[4] = _p.x; X[5] = _p.y; \
      _p = unpk(ACCR[3]); X[6] = _p.x; X[7] = _p.y; }

// ---------------------------------------------------------------------------
// 64x128 GEMM tile (packed f32x2): C[64,128] = A0@W0   (R9-proven structure)
// ---------------------------------------------------------------------------
__device__ __forceinline__ void gemm64p(
    const float* __restrict__ A0,
    const float* __restrict__ W0g,
    float* __restrict__ sW,          // smem, >=1024 floats used
    u64 acc[4][4], int tid)
{
    const int ty = tid >> 4, tx = tid & 15;
    const int wr = tid >> 5;
    const int wc = (tid & 31) << 2;

#pragma unroll 1
    for (int kc = 0; kc < 16; kc++) {
        __syncthreads();
        st4(sW + wr * 128 + wc, ld4(W0g + (kc * 8 + wr) * 128 + wc));
        __syncthreads();
#pragma unroll
        for (int k4 = 0; k4 < 8; k4 += 4) {
            float4 a0[4];
#pragma unroll
            for (int r = 0; r < 4; r++)
                a0[r] = ld4(A0 + (ty * 4 + r) * 128 + kc * 8 + k4);
#pragma unroll
            for (int kk = 0; kk < 4; kk++) {
                const int k = k4 + kk;
                ulonglong2 b0a = ld2u64(sW + k * 128 + tx * 4);
                ulonglong2 b0b = ld2u64(sW + k * 128 + 64 + tx * 4);
#pragma unroll
                for (int r = 0; r < 4; r++) {
                    u64 ap = bcast2((&a0[r].x)[kk]);
                    PFMA8(acc[r], ap, b0a, b0b);
                }
            }
        }
    }
}

// Dual-OUTPUT variant: accS = A@W0, accD = A@W1 (shares A loads).
__device__ __forceinline__ void gemm64p_2w(
    const float* __restrict__ A0,
    const float* __restrict__ W0g, const float* __restrict__ W1g,
    float* __restrict__ sW, u64 accS[4][4], u64 accD[4][4], int tid)
{
    const int ty = tid >> 4, tx = tid & 15;
    const int wr = tid >> 5;
    const int wc = (tid & 31) << 2;

#pragma unroll 1
    for (int kc = 0; kc < 16; kc++) {
        __syncthreads();
        st4(sW + wr * 128 + wc, ld4(W0g + (kc * 8 + wr) * 128 + wc));
        st4(sW + 1024 + wr * 128 + wc, ld4(W1g + (kc * 8 + wr) * 128 + wc));
        __syncthreads();
#pragma unroll
        for (int k4 = 0; k4 < 8; k4 += 4) {
            float4 a0[4];
#pragma unroll
            for (int r = 0; r < 4; r++)
                a0[r] = ld4(A0 + (ty * 4 + r) * 128 + kc * 8 + k4);
#pragma unroll
            for (int kk = 0; kk < 4; kk++) {
                const int k = k4 + kk;
                ulonglong2 b0a = ld2u64(sW + k * 128 + tx * 4);
                ulonglong2 b0b = ld2u64(sW + k * 128 + 64 + tx * 4);
                ulonglong2 b1a = ld2u64(sW + 1024 + k * 128 + tx * 4);
                ulonglong2 b1b = ld2u64(sW + 1024 + k * 128 + 64 + tx * 4);
#pragma unroll
                for (int r = 0; r < 4; r++) {
                    u64 ap = bcast2((&a0[r].x)[kk]);
                    PFMA8(accS[r], ap, b0a, b0b);
                    PFMA8(accD[r], ap, b1a, b1b);
                }
            }
        }
    }
}

// ---------------------------------------------------------------------------
__global__ void zero_upd_kernel() {
    int i = blockIdx.x * blockDim.x + threadIdx.x;
    if (i < NN * HH / 4) reinterpret_cast<float4*>(g_upd)[i] = make_float4(0.f, 0.f, 0.f, 0.f);
}

// Composite weights: g_As = Ws@W1a, g_Gs = Ws@Wg1a, g_Ad = Wd@W1b, g_Gd = Wd@Wg1b
__global__ __launch_bounds__(256, 2) void compose_kernel(
    const float* __restrict__ Ws, const float* __restrict__ Wd,
    const float* __restrict__ W1a, const float* __restrict__ Wg1a,
    const float* __restrict__ W1b, const float* __restrict__ Wg1b)
{
    __shared__ float sA[64 * 128];
    __shared__ float sW[1024];
    const int mat = blockIdx.x >> 1, half = blockIdx.x & 1;
    const float* L = (mat < 2) ? Ws : Wd;
    const float* R = (mat == 0) ? W1a : (mat == 1) ? Wg1a : (mat == 2) ? W1b : Wg1b;
    float* O = (mat == 0) ? g_As : (mat == 1) ? g_Gs : (mat == 2) ? g_Ad : g_Gd;

    const int tid = threadIdx.x, warp = tid >> 5, lane = tid & 31;
    const int ty = tid >> 4, tx = tid & 15;
#pragma unroll
    for (int i = 0; i < 8; i++) {
        int r = warp + i * 8;
        st4(sA + r * 128 + lane * 4, ld4(L + (half * 64 + r) * 128 + lane * 4));
    }
    u64 acc[4][4];
    ZERO_ACC2(acc);
    gemm64p(sA, R, sW, acc, tid);
#pragma unroll
    for (int r = 0; r < 4; r++) {
        int row = half * 64 + ty * 4 + r;
        float x[8]; UNPACK8(x, acc[r]);
        st4(O + row * 128 + tx * 4,      make_float4(x[0], x[1], x[2], x[3]));
        st4(O + row * 128 + 64 + tx * 4, make_float4(x[4], x[5], x[6], x[7]));
    }
}

// folded biases: g_fb[0]=b_src@W1a, [1]=b_src@Wg1a, [2]=b_dst@W1b, [3]=b_dst@Wg1b
__global__ void bias_kernel(
    const float* __restrict__ bsrc, const float* __restrict__ bdst,
    const float* __restrict__ W1a, const float* __restrict__ Wg1a,
    const float* __restrict__ W1b, const float* __restrict__ Wg1b)
{
    const int mat = blockIdx.x, n = threadIdx.x;
    const float* bv = (mat < 2) ? bsrc : bdst;
    const float* R = (mat == 0) ? W1a : (mat == 1) ? Wg1a : (mat == 2) ? W1b : Wg1b;
    float s = 0.f;
    for (int j = 0; j < 128; j++) s = fmaf(bv[j], R[j * 128 + n], s);
    g_fb[mat][n] = s;
}

// Node tables: g_Us[n] = [feat@As + fb0 | feat@Gs + fb1]; g_Ud similarly.
__global__ __launch_bounds__(256, 2) void node_kernel(const float* __restrict__ feat)
{
    __shared__ float sF[64 * 128];
    __shared__ float sW[2 * 1024];
    const int tid = threadIdx.x, warp = tid >> 5, lane = tid & 31;
    const int ty = tid >> 4, tx = tid & 15;
    const int which = (blockIdx.x >= 1563) ? 1 : 0;
    const size_t row0 = (size_t)(blockIdx.x - which * 1563) * 64;

    const float* WA = which ? g_Ad : g_As;
    const float* WG = which ? g_Gd : g_Gs;
    const float* f1 = which ? g_fb[2] : g_fb[0];
    const float* fg = which ? g_fb[3] : g_fb[1];
    float* table = which ? g_Ud : g_Us;

#pragma unroll
    for (int i = 0; i < 8; i++) {
        int r = warp + i * 8;
        size_t gr = row0 + r;
        float4 v = make_float4(0.f, 0.f, 0.f, 0.f);
        if (gr < NN) v = ld4(feat + gr * 128 + lane * 4);
        st4(sF + r * 128 + lane * 4, v);
    }
    u64 accU[4][4], accG[4][4];
    ZERO_ACC2(accU); ZERO_ACC2(accG);
    gemm64p_2w(sF, WA, WG, sW, accU, accG, tid);

    float4 b10 = ld4(f1 + tx * 4), b11 = ld4(f1 + 64 + tx * 4);
    float4 bg0 = ld4(fg + tx * 4), bg1v = ld4(fg + 64 + tx * 4);
#pragma unroll
    for (int r = 0; r < 4; r++) {
        size_t gr = row0 + ty * 4 + r;
        if (gr < NN) {
            float xu[8], xg[8];
            UNPACK8(xu, accU[r]); UNPACK8(xg, accG[r]);
            st4(table + gr * 256 + tx * 4,
                make_float4(xu[0] + b10.x, xu[1] + b10.y, xu[2] + b10.z, xu[3] + b10.w));
            st4(table + gr * 256 + 64 + tx * 4,
                make_float4(xu[4] + b11.x, xu[5] + b11.y, xu[6] + b11.z, xu[7] + b11.w));
            st4(table + gr * 256 + 128 + tx * 4,
                make_float4(xg[0] + bg0.x, xg[1] + bg0.y, xg[2] + bg0.z, xg[3] + bg0.w));
            st4(table + gr * 256 + 192 + tx * 4,
                make_float4(xg[4] + bg1v.x, xg[5] + bg1v.y, xg[6] + bg1v.z, xg[7] + bg1v.w));
        }
    }
}

// Fused edge pipeline: gather precomputed linear parts, 2 GEMMs, LN, gated scatter.
__global__ __launch_bounds__(256, 3) void edge_kernel(
    const int* __restrict__ esrc, const int* __restrict__ edst,
    const float* __restrict__ b1,
    const float* __restrict__ W2,  const float* __restrict__ b2,
    const float* __restrict__ W3,  const float* __restrict__ b3,
    const float* __restrict__ lng, const float* __restrict__ lnb,
    const float* __restrict__ bg1, const float* __restrict__ Wg2,
    const float* __restrict__ bg2)
{
    __shared__ float sH[64 * 128];
    __shared__ float sW[1024];
    __shared__ float sGate[64];
    __shared__ int   sDst[64];

    const int tid = threadIdx.x, warp = tid >> 5, lane = tid & 31;
    const int ty = tid >> 4, tx = tid & 15;
    const int e0 = blockIdx.x * 64;

    // ---- gather + h1 + gate pre-reduction ----
    {
        float4 b1v = ld4(b1 + lane * 4);
        float4 bgv = ld4(bg1 + lane * 4);
        float4 wgv = ld4(Wg2 + lane * 4);
#pragma unroll 1
        for (int i = 0; i < 8; i++) {
            int r = warp * 8 + i;
            int s = esrc[e0 + r];
            int d = edst[e0 + r];
            const float* us = g_Us + (size_t)s * 256;
            const float* ud = g_Ud + (size_t)d * 256;
            float4 a = ld4(us + lane * 4);
            float4 bq = ld4(ud + lane * 4);
            float4 a2 = ld4(us + 128 + lane * 4);
            float4 b2q = ld4(ud + 128 + lane * 4);
            float4 h;
            h.x = gelu_exact(a.x + bq.x + b1v.x);
            h.y = gelu_exact(a.y + bq.y + b1v.y);
            h.z = gelu_exact(a.z + bq.z + b1v.z);
            h.w = gelu_exact(a.w + bq.w + b1v.w);
            st4(sH + r * 128 + lane * 4, h);
            float sg = gelu_exact(a2.x + b2q.x + bgv.x) * wgv.x
                     + gelu_exact(a2.y + b2q.y + bgv.y) * wgv.y
                     + gelu_exact(a2.z + b2q.z + bgv.z) * wgv.z
                     + gelu_exact(a2.w + b2q.w + bgv.w) * wgv.w;
#pragma unroll
            for (int off = 1; off < 32; off <<= 1)
                sg += __shfl_xor_sync(0xffffffffu, sg, off);
            if (lane == 0) { sGate[r] = sg; sDst[r] = d; }
        }
    }
    // (gemm64p's leading __syncthreads orders gather writes before reads)

    u64 acc[4][4];

    // ---- h2 = gelu(h1@W2 + b2) -> sH (overwrite after barrier) ----
    ZERO_ACC2(acc);
    gemm64p(sH, W2, sW, acc, tid);
    __syncthreads();   // all reads of h1 done before overwrite
    {
        float4 bb0 = ld4(b2 + tx * 4), bb1 = ld4(b2 + 64 + tx * 4);
#pragma unroll
        for (int r = 0; r < 4; r++) {
            int row = ty * 4 + r;
            float x[8]; UNPACK8(x, acc[r]);
            float4 h;
            h.x = gelu_exact(x[0] + bb0.x); h.y = gelu_exact(x[1] + bb0.y);
            h.z = gelu_exact(x[2] + bb0.z); h.w = gelu_exact(x[3] + bb0.w);
            st4(sH + row * 128 + tx * 4, h);
            h.x = gelu_exact(x[4] + bb1.x); h.y = gelu_exact(x[5] + bb1.y);
            h.z = gelu_exact(x[6] + bb1.z); h.w = gelu_exact(x[7] + bb1.w);
            st4(sH + row * 128 + 64 + tx * 4, h);
        }
    }

    // ---- m = layernorm(h2@W3 + b3); msg = gate*m; vector-red scatter ----
    ZERO_ACC2(acc);
    gemm64p(sH, W3, sW, acc, tid);
    {
        float bg2v = bg2[0];
        float4 b30 = ld4(b3 + tx * 4),  b31 = ld4(b3 + 64 + tx * 4);
        float4 g0  = ld4(lng + tx * 4), g1  = ld4(lng + 64 + tx * 4);
        float4 e0v = ld4(lnb + tx * 4), e1v = ld4(lnb + 64 + tx * 4);
#pragma unroll
        for (int r = 0; r < 4; r++) {
            int row = ty * 4 + r;
            float x[8]; UNPACK8(x, acc[r]);
            x[0] += b30.x; x[1] += b30.y; x[2] += b30.z; x[3] += b30.w;
            x[4] += b31.x; x[5] += b31.y; x[6] += b31.z; x[7] += b31.w;
            float s = 0.f, ss = 0.f;
#pragma unroll
            for (int j = 0; j < 8; j++) { s += x[j]; ss += x[j] * x[j]; }
#pragma unroll
            for (int off = 1; off < 16; off <<= 1) {
                s  += __shfl_xor_sync(0xffffffffu, s, off);
                ss += __shfl_xor_sync(0xffffffffu, ss, off);
            }
            float m = s * 0.0078125f;
            float var = ss * 0.0078125f - m * m;
            float rstd = rsqrtf(var + 1e-5f);
            float gv = 1.0f / (1.0f + expf(-(sGate[row] + bg2v)));
            float* up = g_upd + (size_t)sDst[row] * 128;
            float4 v0 = make_float4(((x[0] - m) * rstd * g0.x + e0v.x) * gv,
                                    ((x[1] - m) * rstd * g0.y + e0v.y) * gv,
                                    ((x[2] - m) * rstd * g0.z + e0v.z) * gv,
                                    ((x[3] - m) * rstd * g0.w + e0v.w) * gv);
            float4 v1 = make_float4(((x[4] - m) * rstd * g1.x + e1v.x) * gv,
                                    ((x[5] - m) * rstd * g1.y + e1v.y) * gv,
                                    ((x[6] - m) * rstd * g1.z + e1v.z) * gv,
                                    ((x[7] - m) * rstd * g1.w + e1v.w) * gv);
            atomicAdd(reinterpret_cast<float4*>(up + tx * 4), v0);
            atomicAdd(reinterpret_cast<float4*>(up + 64 + tx * 4), v1);
        }
    }
}

// out = upd@W_out + b_out
__global__ __launch_bounds__(256, 2) void out_kernel(
    const float* __restrict__ Wout, const float* __restrict__ bout,
    float* __restrict__ out)
{
    __shared__ float sU[64 * 128];
    __shared__ float sW[1024];
    const int tid = threadIdx.x, warp = tid >> 5, lane = tid & 31;
    const int ty = tid >> 4, tx = tid & 15;
    const size_t row0 = (size_t)blockIdx.x * 64;

#pragma unroll
    for (int i = 0; i < 8; i++) {
        int r = warp + i * 8;
        size_t gr = row0 + r;
        float4 v = make_float4(0.f, 0.f, 0.f, 0.f);
        if (gr < NN) v = ld4(g_upd + gr * 128 + lane * 4);
        st4(sU + r * 128 + lane * 4, v);
    }
    u64 acc[4][4];
    ZERO_ACC2(acc);
    gemm64p(sU, Wout, sW, acc, tid);

    float4 b0 = ld4(bout + tx * 4), b1v = ld4(bout + 64 + tx * 4);
#pragma unroll
    for (int r = 0; r < 4; r++) {
        size_t gr = row0 + ty * 4 + r;
        if (gr < NN) {
            float x[8]; UNPACK8(x, acc[r]);
            st4(out + gr * 128 + tx * 4,
                make_float4(x[0] + b0.x, x[1] + b0.y, x[2] + b0.z, x[3] + b0.w));
            st4(out + gr * 128 + 64 + tx * 4,
                make_float4(x[4] + b1v.x, x[5] + b1v.y, x[6] + b1v.z, x[7] + b1v.w));
        }
    }
}

extern "C" void kernel_launch(void* const* d_in, const int* in_sizes, int n_in,
                              void* d_out, int out_size)
{
    const float* feat  = (const float*)d_in[0];
    const int*   esrc  = (const int*)d_in[1];
    const int*   edst  = (const int*)d_in[2];
    const float* W_src = (const float*)d_in[3];
    const float* b_src = (const float*)d_in[4];
    const float* W_dst = (const float*)d_in[5];
    const float* b_dst = (const float*)d_in[6];
    const float* W1a   = (const float*)d_in[7];
    const float* W1b   = (const float*)d_in[8];
    const float* b1    = (const float*)d_in[9];
    const float* W2    = (const float*)d_in[10];
    const float* b2    = (const float*)d_in[11];
    const float* W3    = (const float*)d_in[12];
    const float* b3    = (const float*)d_in[13];
    const float* ln_g  = (const float*)d_in[14];
    const float* ln_b  = (const float*)d_in[15];
    const float* Wg1a  = (const float*)d_in[16];
    const float* Wg1b  = (const float*)d_in[17];
    const float* bg1   = (const float*)d_in[18];
    const float* Wg2   = (const float*)d_in[19];
    const float* bg2   = (const float*)d_in[20];
    const float* W_out = (const float*)d_in[21];
    const float* b_out = (const float*)d_in[22];
    float* out = (float*)d_out;

    compose_kernel<<<8, 256>>>(W_src, W_dst, W1a, Wg1a, W1b, Wg1b);
    bias_kernel<<<4, 128>>>(b_src, b_dst, W1a, Wg1a, W1b, Wg1b);
    zero_upd_kernel<<<(NN * HH / 4 + 255) / 256, 256>>>();
    node_kernel<<<2 * 1563, 256>>>(feat);
    edge_kernel<<<EE / 64, 256>>>(esrc, edst, b1, W2, b2, W3, b3,
                                  ln_g, ln_b, bg1, Wg2, bg2);
    out_kernel<<<(NN + 63) / 64, 256>>>(W_out, b_out, out);
}